// round 9
// baseline (speedup 1.0000x reference)
#include <cuda_runtime.h>
#include <cuda_bf16.h>
#include <math.h>
#include <float.h>
#include <stdint.h>

#define FS        16000.0f
#define N_FILT    80
#define FILT_DIM  251
#define HALF_K    125
#define L_IN      32000
#define L_OUT     (L_IN - FILT_DIM + 1)   // 31750
#define BATCH     32

#define KF        128                      // folded K (126 used, padded)
#define KSTEPS    8                        // KF / 16
#define NT        10                       // 80 / 8 n-tiles
#define MTILE     256                      // l's per CTA (16 m16-tiles)
#define NMT       16
#define NLT       ((L_OUT + MTILE - 1) / MTILE)   // 125
#define THREADS   256
#define NWARP     8

// Folded H fragment-packed: [kstep][ntile][lane] -> uint4
//   .x = hi b0 (H'[f][16ks+2q], [..+1])   .y = hi b1 (k+8)
//   .z = lo b0                            .w = lo b1
__device__ __align__(16) uint4 Hfrag_g[KSTEPS][NT][32];

struct Smem {
    uint4    Sh[NMT][KSTEPS][32];   // A-fragments hi: 65536 B
    uint4    Sl[NMT][KSTEPS][32];   // A-fragments lo: 65536 B
    uint4    Hf[KSTEPS][NT][32];    // 40960 B
    float    xraw[512];             // 506 used
};

// ---------------------------------------------------------------------------
__device__ __forceinline__ uint32_t pack_bf2(__nv_bfloat16 a, __nv_bfloat16 b) {
    __nv_bfloat162 t; t.x = a; t.y = b;
    return *(uint32_t*)&t;
}

__device__ __forceinline__ void mma16816(float d[4],
                                         uint32_t a0, uint32_t a1,
                                         uint32_t a2, uint32_t a3,
                                         uint32_t b0, uint32_t b1) {
    asm volatile(
        "mma.sync.aligned.m16n8k16.row.col.f32.bf16.bf16.f32 "
        "{%0,%1,%2,%3}, {%4,%5,%6,%7}, {%8,%9}, {%0,%1,%2,%3};"
        : "+f"(d[0]), "+f"(d[1]), "+f"(d[2]), "+f"(d[3])
        : "r"(a0), "r"(a1), "r"(a2), "r"(a3), "r"(b0), "r"(b1));
}

// ---------------------------------------------------------------------------
// Kernel 1: build FOLDED taps (reference numerics; averaged window pair,
// validated ~1e-6), split bf16 hi/lo, packed fragment-linear.
// ---------------------------------------------------------------------------
__global__ void build_filters_kernel(const float* __restrict__ norm_f1,
                                     const float* __restrict__ norm_f2,
                                     const float* __restrict__ amplitude)
{
    const int f = blockIdx.x;
    const int t = threadIdx.x;

    const float min_n = 50.0f / FS;
    float f1n = fabsf(norm_f1[f]) + min_n;
    float f2n = f1n + fabsf(norm_f2[f] - f1n) + min_n;
    float f1 = f1n * FS;
    float f2 = f2n * FS;
    float amp = fabsf(amplitude[f]);

    __shared__ float bp[HALF_K];
    __shared__ float red[128];

    const float TWO_PI = 6.283185307179586f;

    float v = -FLT_MAX;
    if (t < HALF_K) {
        float tr = (float)(t + 1) / FS;          // exact integers 1..125 / fs
        float a2 = TWO_PI * f2 * tr;             // fp32 arg like reference
        float a1 = TWO_PI * f1 * tr;
        float s2 = (float)(sin((double)a2) / (double)a2);
        float s1 = (float)(sin((double)a1) / (double)a1);
        float bb = amp * (2.0f * f2 * s2 - 2.0f * f1 * s1);
        bp[t] = bb;
        v = bb;
    }
    float center = amp * (2.0f * f2 - 2.0f * f1);
    v = fmaxf(v, center);

    red[t] = v;
    __syncthreads();
    for (int s = 64; s > 0; s >>= 1) {
        if (t < s) red[t] = fmaxf(red[t], red[t + s]);
        __syncthreads();
    }
    float mx = red[0];

    const int nt   = f >> 3;
    const int lrow = f & 7;

    for (int k = t; k < KF; k += blockDim.x) {
        float hv = 0.0f;
        if (k < HALF_K) {
            double wj  = 0.54 - 0.46 * cos(2.0 * M_PI * (double)k / 250.0);
            double wjm = 0.54 - 0.46 * cos(2.0 * M_PI * (double)(250 - k) / 250.0);
            hv = (bp[HALF_K - 1 - k] / mx) * (float)(0.5 * (wj + wjm));
        } else if (k == HALF_K) {
            hv = center / mx;                    // window = 1.0 at center
        }
        __nv_bfloat16 hi = __float2bfloat16(hv);
        __nv_bfloat16 lo = __float2bfloat16(hv - __bfloat162float(hi));

        int ks = k >> 4, kk = k & 15;
        int bsel = kk >> 3;            // b0 / b1
        int q    = (kk >> 1) & 3;      // thread-in-group
        int e    = kk & 1;             // element within b32
        int lane = lrow * 4 + q;

        __nv_bfloat16* dst = (__nv_bfloat16*)&Hfrag_g[ks][nt][lane];
        dst[bsel * 2 + e]     = hi;    // .x/.y
        dst[4 + bsel * 2 + e] = lo;    // .z/.w
    }
}

// ---------------------------------------------------------------------------
// folded S element: r in [0,256), k in [0,128)
__device__ __forceinline__ float s_at(const float* __restrict__ xr, int r, int k) {
    if (k < HALF_K)  return xr[r + k] + xr[r + 250 - k];
    if (k == HALF_K) return xr[r + HALF_K];
    return 0.0f;
}

// ---------------------------------------------------------------------------
// Kernel 2: folded implicit-GEMM via mma.sync m16n8k16 bf16, 3-pass split.
// CTA: 1 batch x 256 l x 80 f. Warp w owns m-tiles {2w, 2w+1}; B fragments
// (packed hi+lo uint4) are reused across both m-tiles.
// ---------------------------------------------------------------------------
__global__ void __launch_bounds__(THREADS, 1)
sinc_conv_kernel(const float* __restrict__ x, float* __restrict__ out)
{
    extern __shared__ __align__(16) char smem_raw[];
    Smem* S = (Smem*)smem_raw;

    const int b    = blockIdx.y;
    const int l0   = blockIdx.x * MTILE;
    const int tid  = threadIdx.x;
    const int w    = tid >> 5;
    const int lane = tid & 31;

    // ---- stage H fragments (40 KB) ----
    {
        const uint4* src = (const uint4*)Hfrag_g;
        uint4* dst = (uint4*)S->Hf;
        #pragma unroll 10
        for (int i = tid; i < KSTEPS * NT * 32; i += THREADS) dst[i] = src[i];
    }
    // ---- stage raw x window (506 used) ----
    {
        const float* xb = x + (size_t)b * L_IN;
        for (int i = tid; i < 512; i += THREADS) {
            int gi = l0 + i;
            S->xraw[i] = (i < 506 && gi < L_IN) ? xb[gi] : 0.0f;
        }
    }
    __syncthreads();

    // ---- materialize folded S fragments (hi/lo bf16) ----
    {
        const float* xr = S->xraw;
        #pragma unroll 4
        for (int idx = tid; idx < NMT * KSTEPS * 32; idx += THREADS) {
            int ln  = idx & 31;
            int ks  = (idx >> 5) & 7;
            int mt  = idx >> 8;           // 0..15
            int gid = ln >> 2;            // row-in-group
            int tig = ln & 3;             // k-pair index
            int r0  = 16 * mt + gid;
            int k0  = 16 * ks + 2 * tig;

            float e0 = s_at(xr, r0,     k0);
            float e1 = s_at(xr, r0,     k0 + 1);
            float e2 = s_at(xr, r0 + 8, k0);
            float e3 = s_at(xr, r0 + 8, k0 + 1);
            float e4 = s_at(xr, r0,     k0 + 8);
            float e5 = s_at(xr, r0,     k0 + 9);
            float e6 = s_at(xr, r0 + 8, k0 + 8);
            float e7 = s_at(xr, r0 + 8, k0 + 9);

            __nv_bfloat16 h0 = __float2bfloat16(e0), h1 = __float2bfloat16(e1);
            __nv_bfloat16 h2 = __float2bfloat16(e2), h3 = __float2bfloat16(e3);
            __nv_bfloat16 h4 = __float2bfloat16(e4), h5 = __float2bfloat16(e5);
            __nv_bfloat16 h6 = __float2bfloat16(e6), h7 = __float2bfloat16(e7);

            uint4 hv, lv;
            hv.x = pack_bf2(h0, h1);
            hv.y = pack_bf2(h2, h3);
            hv.z = pack_bf2(h4, h5);
            hv.w = pack_bf2(h6, h7);
            lv.x = pack_bf2(__float2bfloat16(e0 - __bfloat162float(h0)),
                            __float2bfloat16(e1 - __bfloat162float(h1)));
            lv.y = pack_bf2(__float2bfloat16(e2 - __bfloat162float(h2)),
                            __float2bfloat16(e3 - __bfloat162float(h3)));
            lv.z = pack_bf2(__float2bfloat16(e4 - __bfloat162float(h4)),
                            __float2bfloat16(e5 - __bfloat162float(h5)));
            lv.w = pack_bf2(__float2bfloat16(e6 - __bfloat162float(h6)),
                            __float2bfloat16(e7 - __bfloat162float(h7)));

            S->Sh[mt][ks][ln] = hv;
            S->Sl[mt][ks][ln] = lv;
        }
    }
    __syncthreads();

    float D[2][NT][4];
    #pragma unroll
    for (int m = 0; m < 2; m++)
        #pragma unroll
        for (int n = 0; n < NT; n++)
            #pragma unroll
            for (int e = 0; e < 4; e++)
                D[m][n][e] = 0.0f;

    const int mt0 = 2 * w;

    #pragma unroll 1
    for (int ks = 0; ks < KSTEPS; ks++) {
        uint4 Ah0 = S->Sh[mt0][ks][lane];
        uint4 Al0 = S->Sl[mt0][ks][lane];
        uint4 Ah1 = S->Sh[mt0 + 1][ks][lane];
        uint4 Al1 = S->Sl[mt0 + 1][ks][lane];
        #pragma unroll
        for (int n = 0; n < NT; n++) {
            uint4 Bf = S->Hf[ks][n][lane];   // x,y = hi; z,w = lo
            mma16816(D[0][n], Ah0.x, Ah0.y, Ah0.z, Ah0.w, Bf.x, Bf.y);  // hh*sh
            mma16816(D[0][n], Al0.x, Al0.y, Al0.z, Al0.w, Bf.x, Bf.y);  // hh*sl
            mma16816(D[0][n], Ah0.x, Ah0.y, Ah0.z, Ah0.w, Bf.z, Bf.w);  // hl*sh
            mma16816(D[1][n], Ah1.x, Ah1.y, Ah1.z, Ah1.w, Bf.x, Bf.y);
            mma16816(D[1][n], Al1.x, Al1.y, Al1.z, Al1.w, Bf.x, Bf.y);
            mma16816(D[1][n], Ah1.x, Ah1.y, Ah1.z, Ah1.w, Bf.z, Bf.w);
        }
    }

    // ---- store: m-tile mt covers l = l0 + 16*mt + rp (+8); f = 8n+2q (+1) ----
    const int rp = lane >> 2;
    const int q  = lane & 3;
    float* ob = out + (size_t)b * N_FILT * L_OUT;
    #pragma unroll
    for (int m = 0; m < 2; m++) {
        const int l = l0 + 16 * (mt0 + m) + rp;
        #pragma unroll
        for (int n = 0; n < NT; n++) {
            int f = n * 8 + q * 2;
            if (l < L_OUT) {
                ob[(size_t)f * L_OUT + l]       = D[m][n][0];
                ob[(size_t)(f + 1) * L_OUT + l] = D[m][n][1];
            }
            if (l + 8 < L_OUT) {
                ob[(size_t)f * L_OUT + l + 8]       = D[m][n][2];
                ob[(size_t)(f + 1) * L_OUT + l + 8] = D[m][n][3];
            }
        }
    }
}

// ---------------------------------------------------------------------------
extern "C" void kernel_launch(void* const* d_in, const int* in_sizes, int n_in,
                              void* d_out, int out_size)
{
    const float* x       = (const float*)d_in[0];
    const float* norm_f1 = (const float*)d_in[1];
    const float* norm_f2 = (const float*)d_in[2];
    const float* ampl    = (const float*)d_in[3];
    float* out = (float*)d_out;

    cudaFuncSetAttribute(sinc_conv_kernel,
                         cudaFuncAttributeMaxDynamicSharedMemorySize,
                         (int)sizeof(Smem));

    build_filters_kernel<<<N_FILT, 128>>>(norm_f1, norm_f2, ampl);

    dim3 grid(NLT, BATCH);   // (125, 32)
    sinc_conv_kernel<<<grid, THREADS, sizeof(Smem)>>>(x, out);
}

// round 10
// speedup vs baseline: 1.6062x; 1.6062x over previous
#include <cuda_runtime.h>
#include <cuda_bf16.h>
#include <math.h>
#include <float.h>
#include <stdint.h>

#define FS        16000.0f
#define N_FILT    80
#define FILT_DIM  251
#define HALF_K    125
#define L_IN      32000
#define L_OUT     (L_IN - FILT_DIM + 1)   // 31750
#define BATCH     32

#define KF        128                      // folded K (126 used, padded)
#define KSTEPS    8                        // KF / 16
#define NT        10                       // 80 / 8 n-tiles
#define MTILE     128                      // l's per CTA (8 m16-tiles)
#define NMT       8
#define NLT       ((L_OUT + MTILE - 1) / MTILE)   // 249
#define THREADS   256
#define NWARP     8

// Folded H fragment-packed: [kstep][ntile][lane] -> uint4
//   .x = hi b0 (H'[f][16ks+2q], [..+1])   .y = hi b1 (k+8)
//   .z = lo b0                            .w = lo b1
__device__ __align__(16) uint4 Hfrag_g[KSTEPS][NT][32];

struct Smem {
    uint4    Sh[NMT][KSTEPS][32];   // A-fragments hi: 32768 B
    uint4    Sl[NMT][KSTEPS][32];   // A-fragments lo: 32768 B
    float    xraw[384];             // 378 used
};

// ---------------------------------------------------------------------------
__device__ __forceinline__ uint32_t pack_bf2(__nv_bfloat16 a, __nv_bfloat16 b) {
    __nv_bfloat162 t; t.x = a; t.y = b;
    return *(uint32_t*)&t;
}

__device__ __forceinline__ void mma16816(float d[4],
                                         uint32_t a0, uint32_t a1,
                                         uint32_t a2, uint32_t a3,
                                         uint32_t b0, uint32_t b1) {
    asm volatile(
        "mma.sync.aligned.m16n8k16.row.col.f32.bf16.bf16.f32 "
        "{%0,%1,%2,%3}, {%4,%5,%6,%7}, {%8,%9}, {%0,%1,%2,%3};"
        : "+f"(d[0]), "+f"(d[1]), "+f"(d[2]), "+f"(d[3])
        : "r"(a0), "r"(a1), "r"(a2), "r"(a3), "r"(b0), "r"(b1));
}

// ---------------------------------------------------------------------------
// Kernel 1: build FOLDED taps (reference numerics; averaged window pair,
// validated ~1e-6), split bf16 hi/lo, packed fragment-linear.
// ---------------------------------------------------------------------------
__global__ void build_filters_kernel(const float* __restrict__ norm_f1,
                                     const float* __restrict__ norm_f2,
                                     const float* __restrict__ amplitude)
{
    const int f = blockIdx.x;
    const int t = threadIdx.x;

    const float min_n = 50.0f / FS;
    float f1n = fabsf(norm_f1[f]) + min_n;
    float f2n = f1n + fabsf(norm_f2[f] - f1n) + min_n;
    float f1 = f1n * FS;
    float f2 = f2n * FS;
    float amp = fabsf(amplitude[f]);

    __shared__ float bp[HALF_K];
    __shared__ float red[128];

    const float TWO_PI = 6.283185307179586f;

    float v = -FLT_MAX;
    if (t < HALF_K) {
        float tr = (float)(t + 1) / FS;          // exact integers 1..125 / fs
        float a2 = TWO_PI * f2 * tr;             // fp32 arg like reference
        float a1 = TWO_PI * f1 * tr;
        float s2 = (float)(sin((double)a2) / (double)a2);
        float s1 = (float)(sin((double)a1) / (double)a1);
        float bb = amp * (2.0f * f2 * s2 - 2.0f * f1 * s1);
        bp[t] = bb;
        v = bb;
    }
    float center = amp * (2.0f * f2 - 2.0f * f1);
    v = fmaxf(v, center);

    red[t] = v;
    __syncthreads();
    for (int s = 64; s > 0; s >>= 1) {
        if (t < s) red[t] = fmaxf(red[t], red[t + s]);
        __syncthreads();
    }
    float mx = red[0];

    const int nt   = f >> 3;
    const int lrow = f & 7;

    for (int k = t; k < KF; k += blockDim.x) {
        float hv = 0.0f;
        if (k < HALF_K) {
            double wj  = 0.54 - 0.46 * cos(2.0 * M_PI * (double)k / 250.0);
            double wjm = 0.54 - 0.46 * cos(2.0 * M_PI * (double)(250 - k) / 250.0);
            hv = (bp[HALF_K - 1 - k] / mx) * (float)(0.5 * (wj + wjm));
        } else if (k == HALF_K) {
            hv = center / mx;                    // window = 1.0 at center
        }
        __nv_bfloat16 hi = __float2bfloat16(hv);
        __nv_bfloat16 lo = __float2bfloat16(hv - __bfloat162float(hi));

        int ks = k >> 4, kk = k & 15;
        int bsel = kk >> 3;            // b0 / b1
        int q    = (kk >> 1) & 3;      // thread-in-group
        int e    = kk & 1;             // element within b32
        int lane = lrow * 4 + q;

        __nv_bfloat16* dst = (__nv_bfloat16*)&Hfrag_g[ks][nt][lane];
        dst[bsel * 2 + e]     = hi;    // .x/.y
        dst[4 + bsel * 2 + e] = lo;    // .z/.w
    }
}

// ---------------------------------------------------------------------------
// folded S element: r in [0,128), k in [0,128)
__device__ __forceinline__ float s_at(const float* __restrict__ xr, int r, int k) {
    if (k < HALF_K)  return xr[r + k] + xr[r + 250 - k];
    if (k == HALF_K) return xr[r + HALF_K];
    return 0.0f;
}

// ---------------------------------------------------------------------------
// Kernel 2: folded implicit-GEMM via mma.sync m16n8k16 bf16, 3-pass split.
// CTA: 1 batch x 128 l x 80 f, 8 warps. Warp w = (m-pair w&3, n-half w>>2):
// handles m-tiles {2mp, 2mp+1} x n-tiles [5nh, 5nh+5). B fragments are read
// straight from global (L1/L2-hot, shared by all CTAs) and reused across the
// 2 m-tiles.
// ---------------------------------------------------------------------------
__global__ void __launch_bounds__(THREADS, 3)
sinc_conv_kernel(const float* __restrict__ x, float* __restrict__ out)
{
    extern __shared__ __align__(16) char smem_raw[];
    Smem* S = (Smem*)smem_raw;

    const int b    = blockIdx.y;
    const int l0   = blockIdx.x * MTILE;
    const int tid  = threadIdx.x;
    const int w    = tid >> 5;
    const int lane = tid & 31;

    // ---- stage raw x window (378 used) ----
    {
        const float* xb = x + (size_t)b * L_IN;
        for (int i = tid; i < 384; i += THREADS) {
            int gi = l0 + i;
            S->xraw[i] = (i < 378 && gi < L_IN) ? xb[gi] : 0.0f;
        }
    }
    __syncthreads();

    // ---- materialize folded S fragments (hi/lo bf16) ----
    {
        const float* xr = S->xraw;
        #pragma unroll 2
        for (int idx = tid; idx < NMT * KSTEPS * 32; idx += THREADS) {
            int ln  = idx & 31;
            int ks  = (idx >> 5) & 7;
            int mt  = idx >> 8;           // 0..7
            int gid = ln >> 2;            // row-in-group
            int tig = ln & 3;             // k-pair index
            int r0  = 16 * mt + gid;
            int k0  = 16 * ks + 2 * tig;

            float e0 = s_at(xr, r0,     k0);
            float e1 = s_at(xr, r0,     k0 + 1);
            float e2 = s_at(xr, r0 + 8, k0);
            float e3 = s_at(xr, r0 + 8, k0 + 1);
            float e4 = s_at(xr, r0,     k0 + 8);
            float e5 = s_at(xr, r0,     k0 + 9);
            float e6 = s_at(xr, r0 + 8, k0 + 8);
            float e7 = s_at(xr, r0 + 8, k0 + 9);

            __nv_bfloat16 h0 = __float2bfloat16(e0), h1 = __float2bfloat16(e1);
            __nv_bfloat16 h2 = __float2bfloat16(e2), h3 = __float2bfloat16(e3);
            __nv_bfloat16 h4 = __float2bfloat16(e4), h5 = __float2bfloat16(e5);
            __nv_bfloat16 h6 = __float2bfloat16(e6), h7 = __float2bfloat16(e7);

            uint4 hv, lv;
            hv.x = pack_bf2(h0, h1);                 // a0: (r,k),(r,k+1)
            hv.y = pack_bf2(h2, h3);                 // a1: rows +8
            hv.z = pack_bf2(h4, h5);                 // a2: cols +8
            hv.w = pack_bf2(h6, h7);                 // a3: rows+8, cols+8
            lv.x = pack_bf2(__float2bfloat16(e0 - __bfloat162float(h0)),
                            __float2bfloat16(e1 - __bfloat162float(h1)));
            lv.y = pack_bf2(__float2bfloat16(e2 - __bfloat162float(h2)),
                            __float2bfloat16(e3 - __bfloat162float(h3)));
            lv.z = pack_bf2(__float2bfloat16(e4 - __bfloat162float(h4)),
                            __float2bfloat16(e5 - __bfloat162float(h5)));
            lv.w = pack_bf2(__float2bfloat16(e6 - __bfloat162float(h6)),
                            __float2bfloat16(e7 - __bfloat162float(h7)));

            S->Sh[mt][ks][ln] = hv;
            S->Sl[mt][ks][ln] = lv;
        }
    }
    __syncthreads();

    const int mp = w & 3;          // m-pair: m-tiles 2mp, 2mp+1
    const int nh = w >> 2;         // n-half: n-tiles 5nh .. 5nh+4

    float D[2][5][4];
    #pragma unroll
    for (int m = 0; m < 2; m++)
        #pragma unroll
        for (int n = 0; n < 5; n++)
            #pragma unroll
            for (int e = 0; e < 4; e++)
                D[m][n][e] = 0.0f;

    #pragma unroll 1
    for (int ks = 0; ks < KSTEPS; ks++) {
        uint4 Ah0 = S->Sh[2 * mp][ks][lane];
        uint4 Al0 = S->Sl[2 * mp][ks][lane];
        uint4 Ah1 = S->Sh[2 * mp + 1][ks][lane];
        uint4 Al1 = S->Sl[2 * mp + 1][ks][lane];
        const uint4* __restrict__ Hp = &Hfrag_g[ks][5 * nh][lane];
        #pragma unroll
        for (int n = 0; n < 5; n++) {
            uint4 Bf = Hp[n * 32];          // LDG.128, L1/L2-hot
            mma16816(D[0][n], Ah0.x, Ah0.y, Ah0.z, Ah0.w, Bf.x, Bf.y);  // hh*sh
            mma16816(D[0][n], Al0.x, Al0.y, Al0.z, Al0.w, Bf.x, Bf.y);  // hh*sl
            mma16816(D[0][n], Ah0.x, Ah0.y, Ah0.z, Ah0.w, Bf.z, Bf.w);  // hl*sh
            mma16816(D[1][n], Ah1.x, Ah1.y, Ah1.z, Ah1.w, Bf.x, Bf.y);
            mma16816(D[1][n], Al1.x, Al1.y, Al1.z, Al1.w, Bf.x, Bf.y);
            mma16816(D[1][n], Ah1.x, Ah1.y, Ah1.z, Ah1.w, Bf.z, Bf.w);
        }
    }

    // ---- store: m-tile (2mp+m) covers l = l0+16(2mp+m)+rp (+8); f = 8(5nh+n)+2q ----
    const int rp = lane >> 2;
    const int q  = lane & 3;
    float* ob = out + (size_t)b * N_FILT * L_OUT;
    #pragma unroll
    for (int m = 0; m < 2; m++) {
        const int l = l0 + 16 * (2 * mp + m) + rp;
        #pragma unroll
        for (int n = 0; n < 5; n++) {
            int f = (5 * nh + n) * 8 + q * 2;
            if (l < L_OUT) {
                ob[(size_t)f * L_OUT + l]       = D[m][n][0];
                ob[(size_t)(f + 1) * L_OUT + l] = D[m][n][1];
            }
            if (l + 8 < L_OUT) {
                ob[(size_t)f * L_OUT + l + 8]       = D[m][n][2];
                ob[(size_t)(f + 1) * L_OUT + l + 8] = D[m][n][3];
            }
        }
    }
}

// ---------------------------------------------------------------------------
extern "C" void kernel_launch(void* const* d_in, const int* in_sizes, int n_in,
                              void* d_out, int out_size)
{
    const float* x       = (const float*)d_in[0];
    const float* norm_f1 = (const float*)d_in[1];
    const float* norm_f2 = (const float*)d_in[2];
    const float* ampl    = (const float*)d_in[3];
    float* out = (float*)d_out;

    cudaFuncSetAttribute(sinc_conv_kernel,
                         cudaFuncAttributeMaxDynamicSharedMemorySize,
                         (int)sizeof(Smem));

    build_filters_kernel<<<N_FILT, 128>>>(norm_f1, norm_f2, ampl);

    dim3 grid(NLT, BATCH);   // (249, 32)
    sinc_conv_kernel<<<grid, THREADS, sizeof(Smem)>>>(x, out);
}

// round 11
// speedup vs baseline: 1.7854x; 1.1116x over previous
#include <cuda_runtime.h>
#include <cuda_bf16.h>
#include <math.h>
#include <float.h>
#include <stdint.h>

#define FS        16000.0f
#define N_FILT    80
#define FILT_DIM  251
#define HALF_K    125
#define L_IN      32000
#define L_OUT     (L_IN - FILT_DIM + 1)   // 31750
#define BATCH     32

#define KF        128
#define KSTEPS    8
#define NT        10
#define MTILE     128
#define NLT       ((L_OUT + MTILE - 1) / MTILE)   // 249
#define THREADS   256

// Folded H fragment-packed: [kstep][ntile][lane] -> uint4
//   .x = hi b0   .y = hi b1 (k+8)   .z = lo b0   .w = lo b1
__device__ __align__(16) uint4 Hfrag_g[KSTEPS][NT][32];

struct Smem {
    float xf0[258];   // X(l0 + i)
    float xf1[258];   // X(l0 + i + 1)
    float xr0[258];   // X(l0 + 377 - i)
    float xr1[258];   // X(l0 + 376 - i)
};

// ---------------------------------------------------------------------------
__device__ __forceinline__ void mma16816(float d[4],
                                         uint32_t a0, uint32_t a1,
                                         uint32_t a2, uint32_t a3,
                                         uint32_t b0, uint32_t b1) {
    asm volatile(
        "mma.sync.aligned.m16n8k16.row.col.f32.bf16.bf16.f32 "
        "{%0,%1,%2,%3}, {%4,%5,%6,%7}, {%8,%9}, {%0,%1,%2,%3};"
        : "+f"(d[0]), "+f"(d[1]), "+f"(d[2]), "+f"(d[3])
        : "r"(a0), "r"(a1), "r"(a2), "r"(a3), "r"(b0), "r"(b1));
}

// s-pair -> (hi bf16x2, lo bf16x2). lo captures the bf16 remainder.
__device__ __forceinline__ void mk_frag(uint32_t& hi, uint32_t& lo,
                                        float2 a, float2 b) {
    float sx = a.x + b.x;
    float sy = a.y + b.y;
    uint32_t h;
    asm("cvt.rn.bf16x2.f32 %0, %1, %2;" : "=r"(h) : "f"(sy), "f"(sx));
    float hx = __uint_as_float(h << 16);
    float hy = __uint_as_float(h & 0xFFFF0000u);
    float ex = sx - hx;
    float ey = sy - hy;
    asm("cvt.rn.bf16x2.f32 %0, %1, %2;" : "=r"(lo) : "f"(ey), "f"(ex));
    hi = h;
}

// ---------------------------------------------------------------------------
// Kernel 1: build FOLDED taps (reference numerics; averaged window pair).
// NOTE: H'[125] = center/2 because the uniform pair formula in the conv
// kernel produces s(125) = 2*x[l+125].
// ---------------------------------------------------------------------------
__global__ void build_filters_kernel(const float* __restrict__ norm_f1,
                                     const float* __restrict__ norm_f2,
                                     const float* __restrict__ amplitude)
{
    const int f = blockIdx.x;
    const int t = threadIdx.x;

    const float min_n = 50.0f / FS;
    float f1n = fabsf(norm_f1[f]) + min_n;
    float f2n = f1n + fabsf(norm_f2[f] - f1n) + min_n;
    float f1 = f1n * FS;
    float f2 = f2n * FS;
    float amp = fabsf(amplitude[f]);

    __shared__ float bp[HALF_K];
    __shared__ float red[128];

    const float TWO_PI = 6.283185307179586f;

    float v = -FLT_MAX;
    if (t < HALF_K) {
        float tr = (float)(t + 1) / FS;          // exact integers 1..125 / fs
        float a2 = TWO_PI * f2 * tr;             // fp32 arg like reference
        float a1 = TWO_PI * f1 * tr;
        float s2 = (float)(sin((double)a2) / (double)a2);
        float s1 = (float)(sin((double)a1) / (double)a1);
        float bb = amp * (2.0f * f2 * s2 - 2.0f * f1 * s1);
        bp[t] = bb;
        v = bb;
    }
    float center = amp * (2.0f * f2 - 2.0f * f1);
    v = fmaxf(v, center);

    red[t] = v;
    __syncthreads();
    for (int s = 64; s > 0; s >>= 1) {
        if (t < s) red[t] = fmaxf(red[t], red[t + s]);
        __syncthreads();
    }
    float mx = red[0];

    const int nt   = f >> 3;
    const int lrow = f & 7;

    for (int k = t; k < KF; k += blockDim.x) {
        float hv = 0.0f;
        if (k < HALF_K) {
            double wj  = 0.54 - 0.46 * cos(2.0 * M_PI * (double)k / 250.0);
            double wjm = 0.54 - 0.46 * cos(2.0 * M_PI * (double)(250 - k) / 250.0);
            hv = (bp[HALF_K - 1 - k] / mx) * (float)(0.5 * (wj + wjm));
        } else if (k == HALF_K) {
            hv = 0.5f * (center / mx);           // s(125) = 2x -> halve tap
        }
        __nv_bfloat16 hi = __float2bfloat16(hv);
        __nv_bfloat16 lo = __float2bfloat16(hv - __bfloat162float(hi));

        int ks = k >> 4, kk = k & 15;
        int bsel = kk >> 3;
        int q    = (kk >> 1) & 3;
        int e    = kk & 1;
        int lane = lrow * 4 + q;

        __nv_bfloat16* dst = (__nv_bfloat16*)&Hfrag_g[ks][nt][lane];
        dst[bsel * 2 + e]     = hi;    // .x/.y
        dst[4 + bsel * 2 + e] = lo;    // .z/.w
    }
}

// ---------------------------------------------------------------------------
// Kernel 2: folded implicit-GEMM, A-fragments built in registers.
// CTA: 1 batch x 128 l x 80 f, 8 warps. Warp w = (mp = w&3, nh = w>>2):
// m-tiles {2mp, 2mp+1}, n-tiles [5nh, 5nh+5). B straight from global.
// Per warp-kstep: 10 LDS.64 (5 fwd + 5 rev float2 windows, shared across
// both m-tiles) -> 16 fragment u32 via inline bf16 hi/lo split -> 30 MMAs.
// ---------------------------------------------------------------------------
__global__ void __launch_bounds__(THREADS, 2)
sinc_conv_kernel(const float* __restrict__ x, float* __restrict__ out)
{
    extern __shared__ __align__(16) char smem_raw[];
    Smem* S = (Smem*)smem_raw;

    const int b    = blockIdx.y;
    const int l0   = blockIdx.x * MTILE;
    const int tid  = threadIdx.x;
    const int w    = tid >> 5;
    const int lane = tid & 31;

    // ---- stage forward + reversed (and +1 shifted) x copies, clamped ----
    {
        const float* xb = x + (size_t)b * L_IN;
        for (int i = tid; i < 256; i += THREADS) {
            int gf = l0 + i;
            S->xf0[i] = (gf < L_IN) ? xb[gf] : 0.0f;
            S->xf1[i] = (gf + 1 < L_IN) ? xb[gf + 1] : 0.0f;
            int gr = l0 + 377 - i;
            S->xr0[i] = (gr < L_IN) ? xb[gr] : 0.0f;
            int g2 = l0 + 376 - i;
            S->xr1[i] = (g2 < L_IN) ? xb[g2] : 0.0f;
        }
    }
    __syncthreads();

    const int mp  = w & 3;
    const int nh  = w >> 2;
    const int gid = lane >> 2;
    const int tig = lane & 3;
    const int par = gid & 1;        // parity of r (16*mt even)
    const int qq  = 1 - par;        // parity of rev index

    const int rA  = 32 * mp + gid;  // row of m-tile 2mp for this lane

    const float2* Xf = (const float2*)(par ? S->xf1 : S->xf0);
    const float2* Xr = (const float2*)(qq ? S->xr1 : S->xr0);

    float D[2][5][4];
    #pragma unroll
    for (int m = 0; m < 2; m++)
        #pragma unroll
        for (int n = 0; n < 5; n++)
            #pragma unroll
            for (int e = 0; e < 4; e++)
                D[m][n][e] = 0.0f;

    #pragma unroll 1
    for (int ks = 0; ks < KSTEPS; ks++) {
        const int k0 = 16 * ks + 2 * tig;
        const int vb = (rA - par + k0) >> 1;            // fwd f2 word of v = rA+k0
        const int ub = (127 - rA + k0 - 24 - qq) >> 1;  // rev f2 word of u-24

        // fwd window: v, v+8, v+16, v+24, v+32 ; rev: u-24..u+8
        float2 F0 = Xf[vb],      F1 = Xf[vb + 4],  F2 = Xf[vb + 8];
        float2 F3 = Xf[vb + 12], F4 = Xf[vb + 16];
        float2 R0 = Xr[ub],      R1 = Xr[ub + 4],  R2 = Xr[ub + 8];
        float2 R3 = Xr[ub + 12], R4 = Xr[ub + 16];

        // m-tile 2mp   (rows rA, rA+8)
        uint4 Ah0, Al0, Ah1, Al1;
        mk_frag(Ah0.x, Al0.x, F0, R3);   // (r,   k0)
        mk_frag(Ah0.y, Al0.y, F1, R2);   // (r+8, k0)
        mk_frag(Ah0.z, Al0.z, F1, R4);   // (r,   k0+8)
        mk_frag(Ah0.w, Al0.w, F2, R3);   // (r+8, k0+8)
        // m-tile 2mp+1 (rows rA+16, rA+24)
        mk_frag(Ah1.x, Al1.x, F2, R1);
        mk_frag(Ah1.y, Al1.y, F3, R0);
        mk_frag(Ah1.z, Al1.z, F3, R2);
        mk_frag(Ah1.w, Al1.w, F4, R1);

        const uint4* __restrict__ Hp = &Hfrag_g[ks][5 * nh][lane];
        #pragma unroll
        for (int n = 0; n < 5; n++) {
            uint4 Bf = Hp[n * 32];          // LDG.128, L1/L2-hot
            mma16816(D[0][n], Ah0.x, Ah0.y, Ah0.z, Ah0.w, Bf.x, Bf.y);  // hh*sh
            mma16816(D[0][n], Al0.x, Al0.y, Al0.z, Al0.w, Bf.x, Bf.y);  // hh*sl
            mma16816(D[0][n], Ah0.x, Ah0.y, Ah0.z, Ah0.w, Bf.z, Bf.w);  // hl*sh
            mma16816(D[1][n], Ah1.x, Ah1.y, Ah1.z, Ah1.w, Bf.x, Bf.y);
            mma16816(D[1][n], Al1.x, Al1.y, Al1.z, Al1.w, Bf.x, Bf.y);
            mma16816(D[1][n], Ah1.x, Ah1.y, Ah1.z, Ah1.w, Bf.z, Bf.w);
        }
    }

    // ---- store: m-tile (2mp+m) covers l = l0+16(2mp+m)+rp (+8); f = 8(5nh+n)+2q ----
    const int rp = lane >> 2;
    const int q  = lane & 3;
    float* ob = out + (size_t)b * N_FILT * L_OUT;
    #pragma unroll
    for (int m = 0; m < 2; m++) {
        const int l = l0 + 16 * (2 * mp + m) + rp;
        #pragma unroll
        for (int n = 0; n < 5; n++) {
            int f = (5 * nh + n) * 8 + q * 2;
            if (l < L_OUT) {
                ob[(size_t)f * L_OUT + l]       = D[m][n][0];
                ob[(size_t)(f + 1) * L_OUT + l] = D[m][n][1];
            }
            if (l + 8 < L_OUT) {
                ob[(size_t)f * L_OUT + l + 8]       = D[m][n][2];
                ob[(size_t)(f + 1) * L_OUT + l + 8] = D[m][n][3];
            }
        }
    }
}

// ---------------------------------------------------------------------------
extern "C" void kernel_launch(void* const* d_in, const int* in_sizes, int n_in,
                              void* d_out, int out_size)
{
    const float* x       = (const float*)d_in[0];
    const float* norm_f1 = (const float*)d_in[1];
    const float* norm_f2 = (const float*)d_in[2];
    const float* ampl    = (const float*)d_in[3];
    float* out = (float*)d_out;

    cudaFuncSetAttribute(sinc_conv_kernel,
                         cudaFuncAttributeMaxDynamicSharedMemorySize,
                         (int)sizeof(Smem));

    build_filters_kernel<<<N_FILT, 128>>>(norm_f1, norm_f2, ampl);

    dim3 grid(NLT, BATCH);   // (249, 32)
    sinc_conv_kernel<<<grid, THREADS, sizeof(Smem)>>>(x, out);
}